// round 12
// baseline (speedup 1.0000x reference)
#include <cuda_runtime.h>
#include <math.h>
#include <stdint.h>

#define NB 2
#define NS 2048
#define ND 1024
#define NH 16
#define HD 64
#define BHN 32
#define OUT_ELEMS (NB*NS*ND)

// ---------------- scratch ----------------
__device__ float g_q[BHN*NS*HD];
__device__ float g_k[BHN*NS*HD];
__device__ float g_vt[BHN*HD*NS];     // V transposed [bh][d][s]
__device__ float g_oh[NB*NS*ND];      // attention out, token-major
__device__ float g_sq[BHN*NS];
__device__ float g_d2c[BHN*NS];
__device__ float g_mmd[BHN*NS];
__device__ float g_tls[BHN*NS];
__device__ float g_rm[BHN*NS];
__device__ float g_rl[BHN*NS];
__device__ float g_d2cmax[BHN];
__device__ unsigned char g_land[BHN*NS];

// ---------------- mma.sync helpers (baseline PTX, sm_80+) ----------------
__device__ __forceinline__ void mma8(float c[4], const uint32_t a[4], const uint32_t b[2]) {
    asm volatile("mma.sync.aligned.m16n8k8.row.col.f32.tf32.tf32.f32 "
        "{%0,%1,%2,%3}, {%4,%5,%6,%7}, {%8,%9}, {%0,%1,%2,%3};\n"
        : "+f"(c[0]), "+f"(c[1]), "+f"(c[2]), "+f"(c[3])
        : "r"(a[0]), "r"(a[1]), "r"(a[2]), "r"(a[3]), "r"(b[0]), "r"(b[1]));
}
__device__ __forceinline__ void split1(float a, uint32_t& h, uint32_t& l) {
    uint32_t hh, ll;
    asm("cvt.rna.tf32.f32 %0, %1;" : "=r"(hh) : "f"(a));
    float r = a - __uint_as_float(hh);
    asm("cvt.rna.tf32.f32 %0, %1;" : "=r"(ll) : "f"(r));
    h = hh; l = ll;
}
__device__ __forceinline__ void split4(float4 v, uint4& h, uint4& l) {
    split1(v.x, h.x, l.x); split1(v.y, h.y, l.y); split1(v.z, h.z, l.z); split1(v.w, h.w, l.w);
}
// A fragment (m16 k8) from smem[m][S]
__device__ __forceinline__ void lda(uint32_t f[4], const float* A, int m, int k, int S, int gr, int tc) {
    f[0] = __float_as_uint(A[(m+gr)*S + k+tc]);
    f[1] = __float_as_uint(A[(m+gr+8)*S + k+tc]);
    f[2] = __float_as_uint(A[(m+gr)*S + k+tc+4]);
    f[3] = __float_as_uint(A[(m+gr+8)*S + k+tc+4]);
}
// B fragment (k8 n8) from smem[n][S]
__device__ __forceinline__ void ldb(uint32_t f[2], const float* B, int n, int k, int S, int gr, int tc) {
    f[0] = __float_as_uint(B[(n+gr)*S + k+tc]);
    f[1] = __float_as_uint(B[(n+gr)*S + k+tc+4]);
}

// ================= K1/K8: C[tok x feat] = A . W^T + b =================
// mode 0: A=x, W=qkv_w -> q/k head-major + v transposed; mode 1: A=g_oh, W=out_w -> Cout
__global__ void __launch_bounds__(256, 1) k_mm(const float* __restrict__ Ag,
        const float* __restrict__ W, const float* __restrict__ bias,
        float* __restrict__ Cout, int mode)
{
    extern __shared__ float sm[];
    float* Ah = sm;              // [128][33]
    float* Al = Ah + 4224;
    float* Bh = Al + 4224;
    float* Bl = Bh + 4224;
    float* sbias = Bl + 4224;    // [128]
    const int tid = threadIdx.x, lane = tid & 31, wid = tid >> 5;
    const int gr = lane >> 2, tc = lane & 3;
    const int wm = wid & 1, wn = wid >> 1;        // 2 x 4 warp grid, tile 64m x 32n
    const int ft0 = blockIdx.x * 128, tk0 = blockIdx.y * 128;
    const float* A = mode ? (const float*)g_oh : Ag;

    if (tid < 128) sbias[tid] = bias[ft0 + tid];

    float c[4][4][4];
    #pragma unroll
    for (int mt = 0; mt < 4; mt++)
        #pragma unroll
        for (int nt = 0; nt < 4; nt++)
            #pragma unroll
            for (int r = 0; r < 4; r++) c[mt][nt][r] = 0.f;

    for (int c0 = 0; c0 < 1024; c0 += 32) {
        __syncthreads();
        #pragma unroll
        for (int i = 0; i < 4; i++) {
            int idx = tid + 256*i;
            int r = idx >> 3, c4 = (idx & 7) * 4;
            float4 va = *(const float4*)(A + (size_t)(tk0 + r)*1024 + c0 + c4);
            uint4 h, l; split4(va, h, l);
            Ah[r*33 + c4 + 0] = __uint_as_float(h.x); Ah[r*33 + c4 + 1] = __uint_as_float(h.y);
            Ah[r*33 + c4 + 2] = __uint_as_float(h.z); Ah[r*33 + c4 + 3] = __uint_as_float(h.w);
            Al[r*33 + c4 + 0] = __uint_as_float(l.x); Al[r*33 + c4 + 1] = __uint_as_float(l.y);
            Al[r*33 + c4 + 2] = __uint_as_float(l.z); Al[r*33 + c4 + 3] = __uint_as_float(l.w);
            float4 vw = *(const float4*)(W + (size_t)(ft0 + r)*1024 + c0 + c4);
            split4(vw, h, l);
            Bh[r*33 + c4 + 0] = __uint_as_float(h.x); Bh[r*33 + c4 + 1] = __uint_as_float(h.y);
            Bh[r*33 + c4 + 2] = __uint_as_float(h.z); Bh[r*33 + c4 + 3] = __uint_as_float(h.w);
            Bl[r*33 + c4 + 0] = __uint_as_float(l.x); Bl[r*33 + c4 + 1] = __uint_as_float(l.y);
            Bl[r*33 + c4 + 2] = __uint_as_float(l.z); Bl[r*33 + c4 + 3] = __uint_as_float(l.w);
        }
        __syncthreads();
        #pragma unroll
        for (int kt = 0; kt < 4; kt++) {
            int k0 = kt * 8;
            uint32_t ah[4][4], al[4][4], bh2[4][2], bl2[4][2];
            #pragma unroll
            for (int mt = 0; mt < 4; mt++) {
                lda(ah[mt], Ah, wm*64 + mt*16, k0, 33, gr, tc);
                lda(al[mt], Al, wm*64 + mt*16, k0, 33, gr, tc);
            }
            #pragma unroll
            for (int nt = 0; nt < 4; nt++) {
                ldb(bh2[nt], Bh, wn*32 + nt*8, k0, 33, gr, tc);
                ldb(bl2[nt], Bl, wn*32 + nt*8, k0, 33, gr, tc);
            }
            #pragma unroll
            for (int mt = 0; mt < 4; mt++)
                #pragma unroll
                for (int nt = 0; nt < 4; nt++) {
                    mma8(c[mt][nt], ah[mt], bh2[nt]);
                    mma8(c[mt][nt], ah[mt], bl2[nt]);
                    mma8(c[mt][nt], al[mt], bh2[nt]);
                }
        }
    }
    // epilogue
    #pragma unroll
    for (int mt = 0; mt < 4; mt++)
        #pragma unroll
        for (int nt = 0; nt < 4; nt++) {
            int featl = wn*32 + nt*8 + tc*2;
            int feat = ft0 + featl;
            float b0 = sbias[featl], b1 = sbias[featl + 1];
            #pragma unroll
            for (int rr = 0; rr < 2; rr++) {
                int tok = tk0 + wm*64 + mt*16 + gr + rr*8;
                float v0 = c[mt][nt][rr*2]   + b0;
                float v1 = c[mt][nt][rr*2+1] + b1;
                if (mode == 1) {
                    *(float2*)(Cout + (size_t)tok*1024 + feat) = make_float2(v0, v1);
                } else {
                    int which = feat >> 10, hh = (feat >> 6) & 15, d = feat & 63;
                    int b = tok >> 11, s = tok & 2047;
                    if (which == 0)
                        *(float2*)(g_q + ((size_t)(b*NH+hh)*NS + s)*HD + d) = make_float2(v0, v1);
                    else if (which == 1)
                        *(float2*)(g_k + ((size_t)(b*NH+hh)*NS + s)*HD + d) = make_float2(v0, v1);
                    else {
                        g_vt[((size_t)(b*NH+hh)*HD + d    )*NS + s] = v0;
                        g_vt[((size_t)(b*NH+hh)*HD + d + 1)*NS + s] = v1;
                    }
                }
            }
        }
}

// ================= K2: centroid, sq-norm, d2c =================
__global__ void __launch_bounds__(256) k_stats(const float* __restrict__ x) {
    const int bh = blockIdx.x, b = bh >> 4, h = bh & 15, tid = threadIdx.x;
    __shared__ float cent[HD];
    __shared__ float red[256];
    {
        int g = tid >> 6, d = tid & 63;
        float s = 0.f;
        for (int t = g; t < NS; t += 4) s += x[(size_t)(b*NS+t)*ND + h*HD + d];
        red[tid] = s;
        __syncthreads();
        if (tid < 64) cent[tid] = (red[tid]+red[tid+64]+red[tid+128]+red[tid+192]) * (1.0f/NS);
        __syncthreads();
    }
    float lmax = 0.f;
    for (int t = tid; t < NS; t += 256) {
        const float* row = &x[(size_t)(b*NS+t)*ND + h*HD];
        float sq = 0.f, dc = 0.f;
        #pragma unroll
        for (int d = 0; d < HD; d++) { float v = row[d]; sq += v*v; float dd = v - cent[d]; dc += dd*dd; }
        dc = sqrtf(dc);
        g_sq[bh*NS+t] = sq; g_d2c[bh*NS+t] = dc;
        lmax = fmaxf(lmax, dc);
    }
    red[tid] = lmax; __syncthreads();
    for (int s2 = 128; s2 > 0; s2 >>= 1) { if (tid < s2) red[tid] = fmaxf(red[tid], red[tid+s2]); __syncthreads(); }
    if (tid == 0) g_d2cmax[bh] = red[0];
}

// ================= K3: 10-NN via mma =================
__global__ void __launch_bounds__(256, 1) k_knn(const float* __restrict__ x) {
    extern __shared__ float sm[];
    float* Ah = sm;             // [128][65]
    float* Al = Ah + 8320;
    float* Bh = Al + 8320;
    float* Bl = Bh + 8320;
    float* sbuf = Bl + 8320;    // [128][132]
    float* rsq = sbuf + 16896;  // [128]
    float* csq = rsq + 128;     // [128]
    const int tid = threadIdx.x, lane = tid & 31, wid = tid >> 5;
    const int gr = lane >> 2, tc = lane & 3;
    const int wm = wid & 1, wn = wid >> 1;
    const int bh = blockIdx.y, b = bh >> 4, h = bh & 15;
    const int q0 = blockIdx.x * 128;
    const int myrow = tid & 127, half = tid >> 7;

    #pragma unroll
    for (int i = 0; i < 8; i++) {
        int idx = tid + 256*i;
        int r = idx >> 4, c4 = (idx & 15) * 4;
        float4 v = *(const float4*)(x + (size_t)(b*NS + q0 + r)*ND + h*HD + c4);
        uint4 hh, ll; split4(v, hh, ll);
        #pragma unroll
        for (int j = 0; j < 4; j++) {
            Ah[r*65 + c4 + j] = __uint_as_float(((uint32_t*)&hh)[j]);
            Al[r*65 + c4 + j] = __uint_as_float(((uint32_t*)&ll)[j]);
        }
    }
    if (tid < 128) rsq[tid] = g_sq[bh*NS + q0 + tid];

    float best[10];
    #pragma unroll
    for (int i = 0; i < 10; i++) best[i] = 3.0e38f;

    for (int t = 0; t < 16; t++) {
        __syncthreads();
        #pragma unroll
        for (int i = 0; i < 8; i++) {
            int idx = tid + 256*i;
            int r = idx >> 4, c4 = (idx & 15) * 4;
            float4 v = *(const float4*)(x + (size_t)(b*NS + t*128 + r)*ND + h*HD + c4);
            uint4 hh, ll; split4(v, hh, ll);
            #pragma unroll
            for (int j = 0; j < 4; j++) {
                Bh[r*65 + c4 + j] = __uint_as_float(((uint32_t*)&hh)[j]);
                Bl[r*65 + c4 + j] = __uint_as_float(((uint32_t*)&ll)[j]);
            }
        }
        if (tid < 128) csq[tid] = g_sq[bh*NS + t*128 + tid];
        __syncthreads();

        float c[4][4][4];
        #pragma unroll
        for (int mt = 0; mt < 4; mt++)
            #pragma unroll
            for (int nt = 0; nt < 4; nt++)
                #pragma unroll
                for (int r = 0; r < 4; r++) c[mt][nt][r] = 0.f;
        #pragma unroll
        for (int kt = 0; kt < 8; kt++) {
            int k0 = kt * 8;
            uint32_t ah[4][4], al[4][4], bh2[4][2], bl2[4][2];
            #pragma unroll
            for (int mt = 0; mt < 4; mt++) {
                lda(ah[mt], Ah, wm*64 + mt*16, k0, 65, gr, tc);
                lda(al[mt], Al, wm*64 + mt*16, k0, 65, gr, tc);
            }
            #pragma unroll
            for (int nt = 0; nt < 4; nt++) {
                ldb(bh2[nt], Bh, wn*32 + nt*8, k0, 65, gr, tc);
                ldb(bl2[nt], Bl, wn*32 + nt*8, k0, 65, gr, tc);
            }
            #pragma unroll
            for (int mt = 0; mt < 4; mt++)
                #pragma unroll
                for (int nt = 0; nt < 4; nt++) {
                    mma8(c[mt][nt], ah[mt], bh2[nt]);
                    mma8(c[mt][nt], ah[mt], bl2[nt]);
                    mma8(c[mt][nt], al[mt], bh2[nt]);
                }
        }
        #pragma unroll
        for (int mt = 0; mt < 4; mt++)
            #pragma unroll
            for (int nt = 0; nt < 4; nt++)
                #pragma unroll
                for (int rr = 0; rr < 2; rr++)
                    #pragma unroll
                    for (int cc = 0; cc < 2; cc++) {
                        int row = wm*64 + mt*16 + gr + rr*8;
                        int col = wn*32 + nt*8 + tc*2 + cc;
                        sbuf[row*132 + col] = c[mt][nt][rr*2 + cc];
                    }
        __syncthreads();
        float rq = rsq[myrow];
        for (int cc = 0; cc < 64; cc++) {
            int col = half*64 + cc;
            float d2 = rq + csq[col] - 2.0f * sbuf[myrow*132 + col];
            if (d2 < best[9]) {
                float v = d2;
                #pragma unroll
                for (int i = 0; i < 10; i++)
                    if (v < best[i]) { float tm = best[i]; best[i] = v; v = tm; }
            }
        }
    }
    __syncthreads();
    #pragma unroll
    for (int i = 0; i < 10; i++) sbuf[myrow*132 + half*10 + i] = best[i];
    __syncthreads();
    if (tid < 128) {
        int ia = 0, ib = 0; float v = 3.0e38f;
        for (int i = 0; i < 10; i++) {
            float av = (ia < 10) ? sbuf[tid*132 + ia]      : 3.0e38f;
            float bv = (ib < 10) ? sbuf[tid*132 + 10 + ib] : 3.0e38f;
            if (av <= bv) { v = av; ia++; } else { v = bv; ib++; }
        }
        g_mmd[bh*NS + q0 + tid] = sqrtf(fmaxf(v, 0.f));
    }
}

// ================= K4: tls =================
__global__ void __launch_bounds__(256) k_tls() {
    const int bh = blockIdx.x, tid = threadIdx.x;
    __shared__ float red[256];
    float lmax = 0.f;
    for (int t = tid; t < NS; t += 256) lmax = fmaxf(lmax, g_mmd[bh*NS+t]);
    red[tid] = lmax; __syncthreads();
    for (int s2 = 128; s2 > 0; s2 >>= 1) { if (tid < s2) red[tid] = fmaxf(red[tid], red[tid+s2]); __syncthreads(); }
    const float mmax = red[0], dmax = g_d2cmax[bh];
    for (int t = tid; t < NS; t += 256)
        g_tls[bh*NS+t] = 0.7f * (g_d2c[bh*NS+t] / (dmax + 1e-8f)) + 0.3f * (g_mmd[bh*NS+t] / (mmax + 1e-8f));
}

// ================= K5: top-675 bitonic =================
__global__ void __launch_bounds__(1024) k_topk() {
    const int bh = blockIdx.x, tid = threadIdx.x;
    __shared__ unsigned long long key[NS];
    for (int i = tid; i < NS; i += 1024) {
        unsigned int u = __float_as_uint(g_tls[bh*NS+i]);
        u = (u & 0x80000000u) ? ~u : (u | 0x80000000u);
        key[i] = ((unsigned long long)u << 32) | (unsigned int)(~(unsigned int)i);
    }
    for (int i = tid; i < NS; i += 1024) g_land[bh*NS+i] = 0;
    __syncthreads();
    for (int k = 2; k <= NS; k <<= 1)
        for (int j = k >> 1; j > 0; j >>= 1) {
            for (int i = tid; i < NS; i += 1024) {
                int ixj = i ^ j;
                if (ixj > i) {
                    unsigned long long a = key[i], bq = key[ixj];
                    bool sw = ((i & k) == 0) ? (a < bq) : (a > bq);
                    if (sw) { key[i] = bq; key[ixj] = a; }
                }
            }
            __syncthreads();
        }
    if (tid < 675) g_land[bh*NS + (unsigned int)(~(unsigned int)(key[tid] & 0xFFFFFFFFu))] = 1;
}

// ================= K6: scores + mask + online softmax =================
__global__ void __launch_bounds__(256, 1) k_scores(float* __restrict__ attn) {
    extern __shared__ float sm[];
    float* Ah = sm;             // [128][65]  q tile
    float* Al = Ah + 8320;
    float* Bh = Al + 8320;      // [128][65]  k tile
    float* Bl = Bh + 8320;
    float* sbuf = Bl + 8320;    // [128][132]
    unsigned char* lnd = (unsigned char*)(sbuf + 16896);  // 128 bytes
    const int tid = threadIdx.x, lane = tid & 31, wid = tid >> 5;
    const int gr = lane >> 2, tc = lane & 3;
    const int wm = wid & 1, wn = wid >> 1;
    const int bh = blockIdx.y, q0 = blockIdx.x * 128;
    const int myrow = tid & 127, half = tid >> 7;

    #pragma unroll
    for (int i = 0; i < 8; i++) {
        int idx = tid + 256*i;
        int r = idx >> 4, c4 = (idx & 15) * 4;
        float4 v = *(const float4*)(g_q + ((size_t)bh*NS + q0 + r)*HD + c4);
        uint4 hh, ll; split4(v, hh, ll);
        #pragma unroll
        for (int j = 0; j < 4; j++) {
            Ah[r*65 + c4 + j] = __uint_as_float(((uint32_t*)&hh)[j]);
            Al[r*65 + c4 + j] = __uint_as_float(((uint32_t*)&ll)[j]);
        }
    }

    float rm = -3.0e38f, rl = 0.f;
    for (int t = 0; t < 16; t++) {
        __syncthreads();
        #pragma unroll
        for (int i = 0; i < 8; i++) {
            int idx = tid + 256*i;
            int r = idx >> 4, c4 = (idx & 15) * 4;
            float4 v = *(const float4*)(g_k + ((size_t)bh*NS + t*128 + r)*HD + c4);
            uint4 hh, ll; split4(v, hh, ll);
            #pragma unroll
            for (int j = 0; j < 4; j++) {
                Bh[r*65 + c4 + j] = __uint_as_float(((uint32_t*)&hh)[j]);
                Bl[r*65 + c4 + j] = __uint_as_float(((uint32_t*)&ll)[j]);
            }
        }
        if (tid < 128) lnd[tid] = g_land[bh*NS + t*128 + tid];
        __syncthreads();

        float c[4][4][4];
        #pragma unroll
        for (int mt = 0; mt < 4; mt++)
            #pragma unroll
            for (int nt = 0; nt < 4; nt++)
                #pragma unroll
                for (int r = 0; r < 4; r++) c[mt][nt][r] = 0.f;
        #pragma unroll
        for (int kt = 0; kt < 8; kt++) {
            int k0 = kt * 8;
            uint32_t ah[4][4], al[4][4], bh2[4][2], bl2[4][2];
            #pragma unroll
            for (int mt = 0; mt < 4; mt++) {
                lda(ah[mt], Ah, wm*64 + mt*16, k0, 65, gr, tc);
                lda(al[mt], Al, wm*64 + mt*16, k0, 65, gr, tc);
            }
            #pragma unroll
            for (int nt = 0; nt < 4; nt++) {
                ldb(bh2[nt], Bh, wn*32 + nt*8, k0, 65, gr, tc);
                ldb(bl2[nt], Bl, wn*32 + nt*8, k0, 65, gr, tc);
            }
            #pragma unroll
            for (int mt = 0; mt < 4; mt++)
                #pragma unroll
                for (int nt = 0; nt < 4; nt++) {
                    mma8(c[mt][nt], ah[mt], bh2[nt]);
                    mma8(c[mt][nt], ah[mt], bl2[nt]);
                    mma8(c[mt][nt], al[mt], bh2[nt]);
                }
        }
        // mask + stage into smem
        #pragma unroll
        for (int mt = 0; mt < 4; mt++)
            #pragma unroll
            for (int nt = 0; nt < 4; nt++)
                #pragma unroll
                for (int rr = 0; rr < 2; rr++)
                    #pragma unroll
                    for (int cc = 0; cc < 2; cc++) {
                        int row = wm*64 + mt*16 + gr + rr*8;
                        int col = wn*32 + nt*8 + tc*2 + cc;
                        int rowg = q0 + row, colg = t*128 + col;
                        float sc = c[mt][nt][rr*2 + cc] * 0.125f;
                        int rel = colg - rowg;
                        bool keep = ((unsigned)(rel + 64) <= 128u) || (lnd[col] != 0);
                        sbuf[row*132 + col] = keep ? sc : -10000.0f;
                    }
        __syncthreads();
        // online (m,l) on the half-row (unmasked only)
        float lm = -3.0e38f;
        for (int cc = 0; cc < 64; cc++) {
            float v = sbuf[myrow*132 + half*64 + cc];
            if (v > -9999.f) lm = fmaxf(lm, v);
        }
        if (lm > rm) { rl *= __expf(rm - lm); rm = lm; }
        for (int cc = 0; cc < 64; cc++) {
            float v = sbuf[myrow*132 + half*64 + cc];
            if (v > -9999.f) rl += __expf(v - rm);
        }
        // coalesced store of raw masked scores
        #pragma unroll
        for (int i = 0; i < 16; i++) {
            int idx = tid + 256*i;
            int row = idx >> 5, c4 = (idx & 31) * 4;
            float4 v = *(float4*)(sbuf + row*132 + c4);
            *(float4*)(attn + ((size_t)bh*NS + q0 + row)*NS + t*128 + c4) = v;
        }
    }
    __syncthreads();
    sbuf[myrow*132 + half] = rm;
    sbuf[myrow*132 + 2 + half] = rl;
    __syncthreads();
    if (tid < 128) {
        float ma = sbuf[tid*132 + 0], mb = sbuf[tid*132 + 1];
        float la = sbuf[tid*132 + 2], lb = sbuf[tid*132 + 3];
        float m = fmaxf(ma, mb);
        float l = la * __expf(ma - m) + lb * __expf(mb - m);
        g_rm[bh*NS + q0 + tid] = m;
        g_rl[bh*NS + q0 + tid] = l;
    }
}

// ================= K7: attn normalize in place + O = P.V =================
__global__ void __launch_bounds__(256, 1) k_av(float* __restrict__ attn) {
    extern __shared__ float sm[];
    float* Ph = sm;              // [128][132]
    float* Pl = Ph + 16896;
    float* Bh = Pl + 16896;      // [64][132]  vt tile
    float* Bl = Bh + 8448;
    float* rowm = Bl + 8448;     // [128]
    float* rinv = rowm + 128;    // [128]
    const int tid = threadIdx.x, lane = tid & 31, wid = tid >> 5;
    const int gr = lane >> 2, tc = lane & 3;
    const int wm = wid & 3, wn = wid >> 2;        // 4 x 2 warp grid, tile 32m x 32n
    const int bh = blockIdx.y, q0 = blockIdx.x * 128;
    const int b = bh >> 4, h = bh & 15;

    if (tid < 128) {
        rowm[tid] = g_rm[bh*NS + q0 + tid];
        rinv[tid] = 1.0f / g_rl[bh*NS + q0 + tid];
    }

    float c[2][4][4];
    #pragma unroll
    for (int mt = 0; mt < 2; mt++)
        #pragma unroll
        for (int nt = 0; nt < 4; nt++)
            #pragma unroll
            for (int r = 0; r < 4; r++) c[mt][nt][r] = 0.f;

    for (int t = 0; t < 16; t++) {
        __syncthreads();
        // p = softmax, write attn in place, stage split into smem
        #pragma unroll
        for (int i = 0; i < 16; i++) {
            int idx = tid + 256*i;
            int row = idx >> 5, c4 = (idx & 31) * 4;
            float4 v = *(float4*)(attn + ((size_t)bh*NS + q0 + row)*NS + t*128 + c4);
            float m = rowm[row], iv = rinv[row];
            v.x = __expf(v.x - m) * iv; v.y = __expf(v.y - m) * iv;
            v.z = __expf(v.z - m) * iv; v.w = __expf(v.w - m) * iv;
            *(float4*)(attn + ((size_t)bh*NS + q0 + row)*NS + t*128 + c4) = v;
            uint4 hh, ll; split4(v, hh, ll);
            #pragma unroll
            for (int j = 0; j < 4; j++) {
                Ph[row*132 + c4 + j] = __uint_as_float(((uint32_t*)&hh)[j]);
                Pl[row*132 + c4 + j] = __uint_as_float(((uint32_t*)&ll)[j]);
            }
        }
        // vt tile [64 d][128 s]
        #pragma unroll
        for (int i = 0; i < 8; i++) {
            int idx = tid + 256*i;
            int d = idx >> 5, c4 = (idx & 31) * 4;
            float4 v = *(const float4*)(g_vt + (size_t)(bh*HD + d)*NS + t*128 + c4);
            uint4 hh, ll; split4(v, hh, ll);
            #pragma unroll
            for (int j = 0; j < 4; j++) {
                Bh[d*132 + c4 + j] = __uint_as_float(((uint32_t*)&hh)[j]);
                Bl[d*132 + c4 + j] = __uint_as_float(((uint32_t*)&ll)[j]);
            }
        }
        __syncthreads();
        #pragma unroll
        for (int kt = 0; kt < 16; kt++) {
            int k0 = kt * 8;
            uint32_t ah[2][4], al[2][4], bh2[4][2], bl2[4][2];
            #pragma unroll
            for (int mt = 0; mt < 2; mt++) {
                lda(ah[mt], Ph, wm*32 + mt*16, k0, 132, gr, tc);
                lda(al[mt], Pl, wm*32 + mt*16, k0, 132, gr, tc);
            }
            #pragma unroll
            for (int nt = 0; nt < 4; nt++) {
                ldb(bh2[nt], Bh, wn*32 + nt*8, k0, 132, gr, tc);
                ldb(bl2[nt], Bl, wn*32 + nt*8, k0, 132, gr, tc);
            }
            #pragma unroll
            for (int mt = 0; mt < 2; mt++)
                #pragma unroll
                for (int nt = 0; nt < 4; nt++) {
                    mma8(c[mt][nt], ah[mt], bh2[nt]);
                    mma8(c[mt][nt], ah[mt], bl2[nt]);
                    mma8(c[mt][nt], al[mt], bh2[nt]);
                }
        }
    }
    // epilogue: O rows -> g_oh token-major
    #pragma unroll
    for (int mt = 0; mt < 2; mt++)
        #pragma unroll
        for (int nt = 0; nt < 4; nt++) {
            int n = wn*32 + nt*8 + tc*2;
            #pragma unroll
            for (int rr = 0; rr < 2; rr++) {
                int m = wm*32 + mt*16 + gr + rr*8;
                *(float2*)(g_oh + ((size_t)(b*NS + q0 + m))*ND + h*HD + n) =
                    make_float2(c[mt][nt][rr*2], c[mt][nt][rr*2+1]);
            }
        }
}

// ---------------------------------------------------------------------------
extern "C" void kernel_launch(void* const* d_in, const int* in_sizes, int n_in,
                              void* d_out, int out_size) {
    const float* x     = (const float*)d_in[0];
    const float* qkv_w = (const float*)d_in[1];
    const float* qkv_b = (const float*)d_in[2];
    const float* out_w = (const float*)d_in[3];
    const float* out_b = (const float*)d_in[4];
    float* out  = (float*)d_out;
    float* attn = out + OUT_ELEMS;

    const int SM_MM = (4*4224 + 128) * 4;                       // 68096
    const int SM_KN = (4*8320 + 16896 + 256) * 4;               // 201728
    const int SM_SC = (4*8320 + 16896 + 32) * 4;                // 200832
    const int SM_AV = (2*16896 + 2*8448 + 256) * 4;             // 203776
    cudaFuncSetAttribute(k_mm,     cudaFuncAttributeMaxDynamicSharedMemorySize, SM_MM);
    cudaFuncSetAttribute(k_knn,    cudaFuncAttributeMaxDynamicSharedMemorySize, SM_KN);
    cudaFuncSetAttribute(k_scores, cudaFuncAttributeMaxDynamicSharedMemorySize, SM_SC);
    cudaFuncSetAttribute(k_av,     cudaFuncAttributeMaxDynamicSharedMemorySize, SM_AV);

    k_mm    <<<dim3(24, 32), 256, SM_MM>>>(x, qkv_w, qkv_b, nullptr, 0);
    k_stats <<<32, 256>>>(x);
    k_knn   <<<dim3(16, 32), 256, SM_KN>>>(x);
    k_tls   <<<32, 256>>>();
    k_topk  <<<32, 1024>>>();
    k_scores<<<dim3(16, 32), 256, SM_SC>>>(attn);
    k_av    <<<dim3(16, 32), 256, SM_AV>>>(attn);
    k_mm    <<<dim3(8, 32), 256, SM_MM>>>(nullptr, out_w, out_b, out, 1);
}

// round 14
// speedup vs baseline: 1.2658x; 1.2658x over previous
#include <cuda_runtime.h>
#include <math.h>
#include <stdint.h>

#define NB 2
#define NS 2048
#define ND 1024
#define NH 16
#define HD 64
#define BHN 32
#define OUT_ELEMS (NB*NS*ND)

// ---------------- scratch ----------------
__device__ float g_q[BHN*NS*HD];
__device__ float g_k[BHN*NS*HD];
__device__ float g_vt[BHN*HD*NS];     // V transposed [bh][d][s]
__device__ float g_oh[NB*NS*ND];      // attention out, token-major
__device__ float g_sq[BHN*NS];
__device__ float g_d2c[BHN*NS];
__device__ float g_mmd[BHN*NS];
__device__ float g_tls[BHN*NS];
__device__ float g_rm[BHN*NS];
__device__ float g_rl[BHN*NS];
__device__ float g_d2cmax[BHN];
__device__ unsigned char g_land[BHN*NS];

// ---------------- tf32 mma helpers (landmark path only) ----------------
__device__ __forceinline__ void mma8(float c[4], const uint32_t a[4], const uint32_t b[2]) {
    asm volatile("mma.sync.aligned.m16n8k8.row.col.f32.tf32.tf32.f32 "
        "{%0,%1,%2,%3}, {%4,%5,%6,%7}, {%8,%9}, {%0,%1,%2,%3};\n"
        : "+f"(c[0]), "+f"(c[1]), "+f"(c[2]), "+f"(c[3])
        : "r"(a[0]), "r"(a[1]), "r"(a[2]), "r"(a[3]), "r"(b[0]), "r"(b[1]));
}
__device__ __forceinline__ void split1(float a, uint32_t& h, uint32_t& l) {
    uint32_t hh, ll;
    asm("cvt.rna.tf32.f32 %0, %1;" : "=r"(hh) : "f"(a));
    float r = a - __uint_as_float(hh);
    asm("cvt.rna.tf32.f32 %0, %1;" : "=r"(ll) : "f"(r));
    h = hh; l = ll;
}
__device__ __forceinline__ void split4(float4 v, uint4& h, uint4& l) {
    split1(v.x, h.x, l.x); split1(v.y, h.y, l.y); split1(v.z, h.z, l.z); split1(v.w, h.w, l.w);
}
__device__ __forceinline__ void lda(uint32_t f[4], const float* A, int m, int k, int S, int gr, int tc) {
    f[0] = __float_as_uint(A[(m+gr)*S + k+tc]);
    f[1] = __float_as_uint(A[(m+gr+8)*S + k+tc]);
    f[2] = __float_as_uint(A[(m+gr)*S + k+tc+4]);
    f[3] = __float_as_uint(A[(m+gr+8)*S + k+tc+4]);
}
__device__ __forceinline__ void ldb(uint32_t f[2], const float* B, int n, int k, int S, int gr, int tc) {
    f[0] = __float_as_uint(B[(n+gr)*S + k+tc]);
    f[1] = __float_as_uint(B[(n+gr)*S + k+tc+4]);
}

// ---------------- bf16 m16n8k16 helpers (bulk GEMM path) ----------------
__device__ __forceinline__ void mma16(float c[4], const uint32_t a[4], const uint32_t b[2]) {
    asm volatile("mma.sync.aligned.m16n8k16.row.col.f32.bf16.bf16.f32 "
        "{%0,%1,%2,%3}, {%4,%5,%6,%7}, {%8,%9}, {%0,%1,%2,%3};\n"
        : "+f"(c[0]), "+f"(c[1]), "+f"(c[2]), "+f"(c[3])
        : "r"(a[0]), "r"(a[1]), "r"(a[2]), "r"(a[3]), "r"(b[0]), "r"(b[1]));
}
// pack two f32 into bf16x2: lower 16 bits = lo (k), upper = hi (k+1)
__device__ __forceinline__ uint32_t pkb(float lo, float hi) {
    uint32_t d;
    asm("cvt.rn.bf16x2.f32 %0, %1, %2;" : "=r"(d) : "f"(hi), "f"(lo));
    return d;
}
// f32x4 (4 consecutive k) -> hi pair-packs + lo(residual) pair-packs
__device__ __forceinline__ void splitb4(float4 v, uint32_t& h01, uint32_t& h23,
                                        uint32_t& l01, uint32_t& l23) {
    h01 = pkb(v.x, v.y);
    h23 = pkb(v.z, v.w);
    float rx = v.x - __uint_as_float(h01 << 16);
    float ry = v.y - __uint_as_float(h01 & 0xFFFF0000u);
    float rz = v.z - __uint_as_float(h23 << 16);
    float rw = v.w - __uint_as_float(h23 & 0xFFFF0000u);
    l01 = pkb(rx, ry);
    l23 = pkb(rz, rw);
}
// A frag (m16 k16) from u32-pair smem [row][S] (S in u32 units, kk = pair index)
__device__ __forceinline__ void lda16(uint32_t f[4], const uint32_t* A, int m, int kk, int S, int gr, int tc) {
    f[0] = A[(m+gr)*S + kk+tc];
    f[1] = A[(m+gr+8)*S + kk+tc];
    f[2] = A[(m+gr)*S + kk+tc+4];
    f[3] = A[(m+gr+8)*S + kk+tc+4];
}
__device__ __forceinline__ void ldb16(uint32_t f[2], const uint32_t* B, int n, int kk, int S, int gr, int tc) {
    f[0] = B[(n+gr)*S + kk+tc];
    f[1] = B[(n+gr)*S + kk+tc+4];
}

// ================= K1/K8: C[tok x feat] = A . W^T + b  (bf16x2) =================
__global__ void __launch_bounds__(256, 1) k_mm(const float* __restrict__ Ag,
        const float* __restrict__ W, const float* __restrict__ bias,
        float* __restrict__ Cout, int mode)
{
    extern __shared__ char smraw[];
    uint32_t* Aph = (uint32_t*)smraw;        // [128][17] u32 pairs (K=32 -> 16 pairs +1 pad)
    uint32_t* Apl = Aph + 2176;
    uint32_t* Bph = Apl + 2176;
    uint32_t* Bpl = Bph + 2176;
    float* sbias = (float*)(Bpl + 2176);     // [128]
    const int tid = threadIdx.x, lane = tid & 31, wid = tid >> 5;
    const int gr = lane >> 2, tc = lane & 3;
    const int wm = wid & 1, wn = wid >> 1;   // 2 x 4 warp grid, tile 64m x 32n
    const int ft0 = blockIdx.x * 128, tk0 = blockIdx.y * 128;
    const float* A = mode ? (const float*)g_oh : Ag;

    if (tid < 128) sbias[tid] = bias[ft0 + tid];

    float c[4][4][4];
    #pragma unroll
    for (int mt = 0; mt < 4; mt++)
        #pragma unroll
        for (int nt = 0; nt < 4; nt++)
            #pragma unroll
            for (int r = 0; r < 4; r++) c[mt][nt][r] = 0.f;

    for (int c0 = 0; c0 < 1024; c0 += 32) {
        __syncthreads();
        #pragma unroll
        for (int i = 0; i < 4; i++) {
            int idx = tid + 256*i;
            int r = idx >> 3, pb = (idx & 7) * 2, kf = (idx & 7) * 4;
            float4 va = *(const float4*)(A + (size_t)(tk0 + r)*1024 + c0 + kf);
            uint32_t h01, h23, l01, l23;
            splitb4(va, h01, h23, l01, l23);
            Aph[r*17 + pb] = h01; Aph[r*17 + pb + 1] = h23;
            Apl[r*17 + pb] = l01; Apl[r*17 + pb + 1] = l23;
            float4 vw = *(const float4*)(W + (size_t)(ft0 + r)*1024 + c0 + kf);
            splitb4(vw, h01, h23, l01, l23);
            Bph[r*17 + pb] = h01; Bph[r*17 + pb + 1] = h23;
            Bpl[r*17 + pb] = l01; Bpl[r*17 + pb + 1] = l23;
        }
        __syncthreads();
        #pragma unroll
        for (int ks = 0; ks < 2; ks++) {
            int kk = ks * 8;
            uint32_t ah[4][4], al[4][4], bh2[4][2], bl2[4][2];
            #pragma unroll
            for (int mt = 0; mt < 4; mt++) {
                lda16(ah[mt], Aph, wm*64 + mt*16, kk, 17, gr, tc);
                lda16(al[mt], Apl, wm*64 + mt*16, kk, 17, gr, tc);
            }
            #pragma unroll
            for (int nt = 0; nt < 4; nt++) {
                ldb16(bh2[nt], Bph, wn*32 + nt*8, kk, 17, gr, tc);
                ldb16(bl2[nt], Bpl, wn*32 + nt*8, kk, 17, gr, tc);
            }
            #pragma unroll
            for (int mt = 0; mt < 4; mt++)
                #pragma unroll
                for (int nt = 0; nt < 4; nt++) {
                    mma16(c[mt][nt], ah[mt], bh2[nt]);
                    mma16(c[mt][nt], ah[mt], bl2[nt]);
                    mma16(c[mt][nt], al[mt], bh2[nt]);
                }
        }
    }
    // epilogue
    #pragma unroll
    for (int mt = 0; mt < 4; mt++)
        #pragma unroll
        for (int nt = 0; nt < 4; nt++) {
            int featl = wn*32 + nt*8 + tc*2;
            int feat = ft0 + featl;
            float b0 = sbias[featl], b1 = sbias[featl + 1];
            #pragma unroll
            for (int rr = 0; rr < 2; rr++) {
                int tok = tk0 + wm*64 + mt*16 + gr + rr*8;
                float v0 = c[mt][nt][rr*2]   + b0;
                float v1 = c[mt][nt][rr*2+1] + b1;
                if (mode == 1) {
                    *(float2*)(Cout + (size_t)tok*1024 + feat) = make_float2(v0, v1);
                } else {
                    int which = feat >> 10, hh = (feat >> 6) & 15, d = feat & 63;
                    int b = tok >> 11, s = tok & 2047;
                    if (which == 0)
                        *(float2*)(g_q + ((size_t)(b*NH+hh)*NS + s)*HD + d) = make_float2(v0, v1);
                    else if (which == 1)
                        *(float2*)(g_k + ((size_t)(b*NH+hh)*NS + s)*HD + d) = make_float2(v0, v1);
                    else {
                        g_vt[((size_t)(b*NH+hh)*HD + d    )*NS + s] = v0;
                        g_vt[((size_t)(b*NH+hh)*HD + d + 1)*NS + s] = v1;
                    }
                }
            }
        }
}

// ================= K2: centroid, sq-norm, d2c =================
__global__ void __launch_bounds__(256) k_stats(const float* __restrict__ x) {
    const int bh = blockIdx.x, b = bh >> 4, h = bh & 15, tid = threadIdx.x;
    __shared__ float cent[HD];
    __shared__ float red[256];
    {
        int g = tid >> 6, d = tid & 63;
        float s = 0.f;
        for (int t = g; t < NS; t += 4) s += x[(size_t)(b*NS+t)*ND + h*HD + d];
        red[tid] = s;
        __syncthreads();
        if (tid < 64) cent[tid] = (red[tid]+red[tid+64]+red[tid+128]+red[tid+192]) * (1.0f/NS);
        __syncthreads();
    }
    float lmax = 0.f;
    for (int t = tid; t < NS; t += 256) {
        const float* row = &x[(size_t)(b*NS+t)*ND + h*HD];
        float sq = 0.f, dc = 0.f;
        #pragma unroll
        for (int d = 0; d < HD; d++) { float v = row[d]; sq += v*v; float dd = v - cent[d]; dc += dd*dd; }
        dc = sqrtf(dc);
        g_sq[bh*NS+t] = sq; g_d2c[bh*NS+t] = dc;
        lmax = fmaxf(lmax, dc);
    }
    red[tid] = lmax; __syncthreads();
    for (int s2 = 128; s2 > 0; s2 >>= 1) { if (tid < s2) red[tid] = fmaxf(red[tid], red[tid+s2]); __syncthreads(); }
    if (tid == 0) g_d2cmax[bh] = red[0];
}

// ================= K3: 10-NN via 3xTF32 mma (precision-critical, unchanged) =================
__global__ void __launch_bounds__(256, 1) k_knn(const float* __restrict__ x) {
    extern __shared__ float sm[];
    float* Ah = sm;             // [128][65]
    float* Al = Ah + 8320;
    float* Bh = Al + 8320;
    float* Bl = Bh + 8320;
    float* sbuf = Bl + 8320;    // [128][132]
    float* rsq = sbuf + 16896;  // [128]
    float* csq = rsq + 128;     // [128]
    const int tid = threadIdx.x, lane = tid & 31, wid = tid >> 5;
    const int gr = lane >> 2, tc = lane & 3;
    const int wm = wid & 1, wn = wid >> 1;
    const int bh = blockIdx.y, b = bh >> 4, h = bh & 15;
    const int q0 = blockIdx.x * 128;
    const int myrow = tid & 127, half = tid >> 7;

    #pragma unroll
    for (int i = 0; i < 8; i++) {
        int idx = tid + 256*i;
        int r = idx >> 4, c4 = (idx & 15) * 4;
        float4 v = *(const float4*)(x + (size_t)(b*NS + q0 + r)*ND + h*HD + c4);
        uint4 hh, ll; split4(v, hh, ll);
        #pragma unroll
        for (int j = 0; j < 4; j++) {
            Ah[r*65 + c4 + j] = __uint_as_float(((uint32_t*)&hh)[j]);
            Al[r*65 + c4 + j] = __uint_as_float(((uint32_t*)&ll)[j]);
        }
    }
    if (tid < 128) rsq[tid] = g_sq[bh*NS + q0 + tid];

    float best[10];
    #pragma unroll
    for (int i = 0; i < 10; i++) best[i] = 3.0e38f;

    for (int t = 0; t < 16; t++) {
        __syncthreads();
        #pragma unroll
        for (int i = 0; i < 8; i++) {
            int idx = tid + 256*i;
            int r = idx >> 4, c4 = (idx & 15) * 4;
            float4 v = *(const float4*)(x + (size_t)(b*NS + t*128 + r)*ND + h*HD + c4);
            uint4 hh, ll; split4(v, hh, ll);
            #pragma unroll
            for (int j = 0; j < 4; j++) {
                Bh[r*65 + c4 + j] = __uint_as_float(((uint32_t*)&hh)[j]);
                Bl[r*65 + c4 + j] = __uint_as_float(((uint32_t*)&ll)[j]);
            }
        }
        if (tid < 128) csq[tid] = g_sq[bh*NS + t*128 + tid];
        __syncthreads();

        float c[4][4][4];
        #pragma unroll
        for (int mt = 0; mt < 4; mt++)
            #pragma unroll
            for (int nt = 0; nt < 4; nt++)
                #pragma unroll
                for (int r = 0; r < 4; r++) c[mt][nt][r] = 0.f;
        #pragma unroll
        for (int kt = 0; kt < 8; kt++) {
            int k0 = kt * 8;
            uint32_t ah[4][4], al[4][4], bh2[4][2], bl2[4][2];
            #pragma unroll
            for (int mt = 0; mt < 4; mt++) {
                lda(ah[mt], Ah, wm*64 + mt*16, k0, 65, gr, tc);
                lda(al[mt], Al, wm*64 + mt*16, k0, 65, gr, tc);
            }
            #pragma unroll
            for (int nt = 0; nt < 4; nt++) {
                ldb(bh2[nt], Bh, wn*32 + nt*8, k0, 65, gr, tc);
                ldb(bl2[nt], Bl, wn*32 + nt*8, k0, 65, gr, tc);
            }
            #pragma unroll
            for (int mt = 0; mt < 4; mt++)
                #pragma unroll
                for (int nt = 0; nt < 4; nt++) {
                    mma8(c[mt][nt], ah[mt], bh2[nt]);
                    mma8(c[mt][nt], ah[mt], bl2[nt]);
                    mma8(c[mt][nt], al[mt], bh2[nt]);
                }
        }
        #pragma unroll
        for (int mt = 0; mt < 4; mt++)
            #pragma unroll
            for (int nt = 0; nt < 4; nt++)
                #pragma unroll
                for (int rr = 0; rr < 2; rr++)
                    #pragma unroll
                    for (int cc = 0; cc < 2; cc++) {
                        int row = wm*64 + mt*16 + gr + rr*8;
                        int col = wn*32 + nt*8 + tc*2 + cc;
                        sbuf[row*132 + col] = c[mt][nt][rr*2 + cc];
                    }
        __syncthreads();
        float rq = rsq[myrow];
        for (int cc = 0; cc < 64; cc++) {
            int col = half*64 + cc;
            float d2 = rq + csq[col] - 2.0f * sbuf[myrow*132 + col];
            if (d2 < best[9]) {
                float v = d2;
                #pragma unroll
                for (int i = 0; i < 10; i++)
                    if (v < best[i]) { float tm = best[i]; best[i] = v; v = tm; }
            }
        }
    }
    __syncthreads();
    #pragma unroll
    for (int i = 0; i < 10; i++) sbuf[myrow*132 + half*10 + i] = best[i];
    __syncthreads();
    if (tid < 128) {
        int ia = 0, ib = 0; float v = 3.0e38f;
        for (int i = 0; i < 10; i++) {
            float av = (ia < 10) ? sbuf[tid*132 + ia]      : 3.0e38f;
            float bv = (ib < 10) ? sbuf[tid*132 + 10 + ib] : 3.0e38f;
            if (av <= bv) { v = av; ia++; } else { v = bv; ib++; }
        }
        g_mmd[bh*NS + q0 + tid] = sqrtf(fmaxf(v, 0.f));
    }
}

// ================= K4: tls =================
__global__ void __launch_bounds__(256) k_tls() {
    const int bh = blockIdx.x, tid = threadIdx.x;
    __shared__ float red[256];
    float lmax = 0.f;
    for (int t = tid; t < NS; t += 256) lmax = fmaxf(lmax, g_mmd[bh*NS+t]);
    red[tid] = lmax; __syncthreads();
    for (int s2 = 128; s2 > 0; s2 >>= 1) { if (tid < s2) red[tid] = fmaxf(red[tid], red[tid+s2]); __syncthreads(); }
    const float mmax = red[0], dmax = g_d2cmax[bh];
    for (int t = tid; t < NS; t += 256)
        g_tls[bh*NS+t] = 0.7f * (g_d2c[bh*NS+t] / (dmax + 1e-8f)) + 0.3f * (g_mmd[bh*NS+t] / (mmax + 1e-8f));
}

// ================= K5: top-675 bitonic =================
__global__ void __launch_bounds__(1024) k_topk() {
    const int bh = blockIdx.x, tid = threadIdx.x;
    __shared__ unsigned long long key[NS];
    for (int i = tid; i < NS; i += 1024) {
        unsigned int u = __float_as_uint(g_tls[bh*NS+i]);
        u = (u & 0x80000000u) ? ~u : (u | 0x80000000u);
        key[i] = ((unsigned long long)u << 32) | (unsigned int)(~(unsigned int)i);
    }
    for (int i = tid; i < NS; i += 1024) g_land[bh*NS+i] = 0;
    __syncthreads();
    for (int k = 2; k <= NS; k <<= 1)
        for (int j = k >> 1; j > 0; j >>= 1) {
            for (int i = tid; i < NS; i += 1024) {
                int ixj = i ^ j;
                if (ixj > i) {
                    unsigned long long a = key[i], bq = key[ixj];
                    bool sw = ((i & k) == 0) ? (a < bq) : (a > bq);
                    if (sw) { key[i] = bq; key[ixj] = a; }
                }
            }
            __syncthreads();
        }
    if (tid < 675) g_land[bh*NS + (unsigned int)(~(unsigned int)(key[tid] & 0xFFFFFFFFu))] = 1;
}

// ================= K6: scores + mask + online softmax (bf16x2) =================
__global__ void __launch_bounds__(256, 1) k_scores(float* __restrict__ attn) {
    extern __shared__ char smraw[];
    uint32_t* Aph = (uint32_t*)smraw;      // [128][33] pairs (K=64 -> 32 pairs +1 pad)
    uint32_t* Apl = Aph + 4224;
    uint32_t* Bph = Apl + 4224;
    uint32_t* Bpl = Bph + 4224;
    float* sbuf = (float*)(Bpl + 4224);    // [128][132]
    unsigned char* lnd = (unsigned char*)(sbuf + 16896);  // 128 bytes
    const int tid = threadIdx.x, lane = tid & 31, wid = tid >> 5;
    const int gr = lane >> 2, tc = lane & 3;
    const int wm = wid & 1, wn = wid >> 1;
    const int bh = blockIdx.y, q0 = blockIdx.x * 128;
    const int myrow = tid & 127, half = tid >> 7;

    #pragma unroll
    for (int i = 0; i < 8; i++) {
        int idx = tid + 256*i;
        int r = idx >> 4, pb = (idx & 15) * 2, kf = (idx & 15) * 4;
        float4 v = *(const float4*)(g_q + ((size_t)bh*NS + q0 + r)*HD + kf);
        uint32_t h01, h23, l01, l23;
        splitb4(v, h01, h23, l01, l23);
        Aph[r*33 + pb] = h01; Aph[r*33 + pb + 1] = h23;
        Apl[r*33 + pb] = l01; Apl[r*33 + pb + 1] = l23;
    }

    float rm = -3.0e38f, rl = 0.f;
    for (int t = 0; t < 16; t++) {
        __syncthreads();
        #pragma unroll
        for (int i = 0; i < 8; i++) {
            int idx = tid + 256*i;
            int r = idx >> 4, pb = (idx & 15) * 2, kf = (idx & 15) * 4;
            float4 v = *(const float4*)(g_k + ((size_t)bh*NS + t*128 + r)*HD + kf);
            uint32_t h01, h23, l01, l23;
            splitb4(v, h01, h23, l01, l23);
            Bph[r*33 + pb] = h01; Bph[r*33 + pb + 1] = h23;
            Bpl[r*33 + pb] = l01; Bpl[r*33 + pb + 1] = l23;
        }
        if (tid < 128) lnd[tid] = g_land[bh*NS + t*128 + tid];
        __syncthreads();

        float c[4][4][4];
        #pragma unroll
        for (int mt = 0; mt < 4; mt++)
            #pragma unroll
            for (int nt = 0; nt < 4; nt++)
                #pragma unroll
                for (int r = 0; r < 4; r++) c[mt][nt][r] = 0.f;
        #pragma unroll
        for (int ks = 0; ks < 4; ks++) {
            int kk = ks * 8;
            uint32_t ah[4][4], al[4][4], bh2[4][2], bl2[4][2];
            #pragma unroll
            for (int mt = 0; mt < 4; mt++) {
                lda16(ah[mt], Aph, wm*64 + mt*16, kk, 33, gr, tc);
                lda16(al[mt], Apl, wm*64 + mt*16, kk, 33, gr, tc);
            }
            #pragma unroll
            for (int nt = 0; nt < 4; nt++) {
                ldb16(bh2[nt], Bph, wn*32 + nt*8, kk, 33, gr, tc);
                ldb16(bl2[nt], Bpl, wn*32 + nt*8, kk, 33, gr, tc);
            }
            #pragma unroll
            for (int mt = 0; mt < 4; mt++)
                #pragma unroll
                for (int nt = 0; nt < 4; nt++) {
                    mma16(c[mt][nt], ah[mt], bh2[nt]);
                    mma16(c[mt][nt], ah[mt], bl2[nt]);
                    mma16(c[mt][nt], al[mt], bh2[nt]);
                }
        }
        // mask + stage into smem
        #pragma unroll
        for (int mt = 0; mt < 4; mt++)
            #pragma unroll
            for (int nt = 0; nt < 4; nt++)
                #pragma unroll
                for (int rr = 0; rr < 2; rr++)
                    #pragma unroll
                    for (int cc = 0; cc < 2; cc++) {
                        int row = wm*64 + mt*16 + gr + rr*8;
                        int col = wn*32 + nt*8 + tc*2 + cc;
                        int rowg = q0 + row, colg = t*128 + col;
                        float sc = c[mt][nt][rr*2 + cc] * 0.125f;
                        int rel = colg - rowg;
                        bool keep = ((unsigned)(rel + 64) <= 128u) || (lnd[col] != 0);
                        sbuf[row*132 + col] = keep ? sc : -10000.0f;
                    }
        __syncthreads();
        // online (m,l) on the half-row (unmasked only)
        float lm = -3.0e38f;
        for (int cc = 0; cc < 64; cc++) {
            float v = sbuf[myrow*132 + half*64 + cc];
            if (v > -9999.f) lm = fmaxf(lm, v);
        }
        if (lm > rm) { rl *= __expf(rm - lm); rm = lm; }
        for (int cc = 0; cc < 64; cc++) {
            float v = sbuf[myrow*132 + half*64 + cc];
            if (v > -9999.f) rl += __expf(v - rm);
        }
        // coalesced store of raw masked scores
        #pragma unroll
        for (int i = 0; i < 16; i++) {
            int idx = tid + 256*i;
            int row = idx >> 5, c4 = (idx & 31) * 4;
            float4 v = *(float4*)(sbuf + row*132 + c4);
            *(float4*)(attn + ((size_t)bh*NS + q0 + row)*NS + t*128 + c4) = v;
        }
    }
    __syncthreads();
    sbuf[myrow*132 + half] = rm;
    sbuf[myrow*132 + 2 + half] = rl;
    __syncthreads();
    if (tid < 128) {
        float ma = sbuf[tid*132 + 0], mb = sbuf[tid*132 + 1];
        float la = sbuf[tid*132 + 2], lb = sbuf[tid*132 + 3];
        float m = fmaxf(ma, mb);
        float l = la * __expf(ma - m) + lb * __expf(mb - m);
        g_rm[bh*NS + q0 + tid] = m;
        g_rl[bh*NS + q0 + tid] = l;
    }
}

// ================= K7: attn normalize in place + O = P.V (bf16x2) =================
__global__ void __launch_bounds__(256, 1) k_av(float* __restrict__ attn) {
    extern __shared__ char smraw[];
    uint32_t* Pph = (uint32_t*)smraw;      // [128][65] pairs (K=128 -> 64 pairs +1 pad)
    uint32_t* Ppl = Pph + 8320;
    uint32_t* Bph = Ppl + 8320;            // [64][65] vt tile
    uint32_t* Bpl = Bph + 4160;
    float* rowm = (float*)(Bpl + 4160);    // [128]
    float* rinv = rowm + 128;              // [128]
    const int tid = threadIdx.x, lane = tid & 31, wid = tid >> 5;
    const int gr = lane >> 2, tc = lane & 3;
    const int wm = wid & 3, wn = wid >> 2;  // 4 x 2 warp grid, tile 32m x 32n
    const int bh = blockIdx.y, q0 = blockIdx.x * 128;
    const int b = bh >> 4, h = bh & 15;

    if (tid < 128) {
        rowm[tid] = g_rm[bh*NS + q0 + tid];
        rinv[tid] = 1.0f / g_rl[bh*NS + q0 + tid];
    }

    float c[2][4][4];
    #pragma unroll
    for (int mt = 0; mt < 2; mt++)
        #pragma unroll
        for (int nt = 0; nt < 4; nt++)
            #pragma unroll
            for (int r = 0; r < 4; r++) c[mt][nt][r] = 0.f;

    for (int t = 0; t < 16; t++) {
        __syncthreads();
        // p = softmax, write attn in place, stage split into smem
        #pragma unroll
        for (int i = 0; i < 16; i++) {
            int idx = tid + 256*i;
            int row = idx >> 5, pb = (idx & 31) * 2, kf = (idx & 31) * 4;
            float4 v = *(float4*)(attn + ((size_t)bh*NS + q0 + row)*NS + t*128 + kf);
            float m = rowm[row], iv = rinv[row];
            v.x = __expf(v.x - m) * iv; v.y = __expf(v.y - m) * iv;
            v.z = __expf(v.z - m) * iv; v.w = __expf(v.w - m) * iv;
            *(float4*)(attn + ((size_t)bh*NS + q0 + row)*NS + t*128 + kf) = v;
            uint32_t h01, h23, l01, l23;
            splitb4(v, h01, h23, l01, l23);
            Pph[row*65 + pb] = h01; Pph[row*65 + pb + 1] = h23;
            Ppl[row*65 + pb] = l01; Ppl[row*65 + pb + 1] = l23;
        }
        // vt tile [64 d][128 s]
        #pragma unroll
        for (int i = 0; i < 8; i++) {
            int idx = tid + 256*i;
            int d = idx >> 5, pb = (idx & 31) * 2, kf = (idx & 31) * 4;
            float4 v = *(const float4*)(g_vt + (size_t)(bh*HD + d)*NS + t*128 + kf);
            uint32_t h01, h23, l01, l23;
            splitb4(v, h01, h23, l01, l23);
            Bph[d*65 + pb] = h01; Bph[d*65 + pb + 1] = h23;
            Bpl[d*65 + pb] = l01; Bpl[d*65 + pb + 1] = l23;
        }
        __syncthreads();
        #pragma unroll
        for (int ks = 0; ks < 8; ks++) {
            int kk = ks * 8;
            uint32_t ah[2][4], al[2][4], bh2[4][2], bl2[4][2];
            #pragma unroll
            for (int mt = 0; mt < 2; mt++) {
                lda16(ah[mt], Pph, wm*32 + mt*16, kk, 65, gr, tc);
                lda16(al[mt], Ppl, wm*32 + mt*16, kk, 65, gr, tc);
            }
            #pragma unroll
            for (int nt = 0; nt < 4; nt++) {
                ldb16(bh2[nt], Bph, wn*32 + nt*8, kk, 65, gr, tc);
                ldb16(bl2[nt], Bpl, wn*32 + nt*8, kk, 65, gr, tc);
            }
            #pragma unroll
            for (int mt = 0; mt < 2; mt++)
                #pragma unroll
                for (int nt = 0; nt < 4; nt++) {
                    mma16(c[mt][nt], ah[mt], bh2[nt]);
                    mma16(c[mt][nt], ah[mt], bl2[nt]);
                    mma16(c[mt][nt], al[mt], bh2[nt]);
                }
        }
    }
    // epilogue: O rows -> g_oh token-major
    #pragma unroll
    for (int mt = 0; mt < 2; mt++)
        #pragma unroll
        for (int nt = 0; nt < 4; nt++) {
            int n = wn*32 + nt*8 + tc*2;
            #pragma unroll
            for (int rr = 0; rr < 2; rr++) {
                int m = wm*32 + mt*16 + gr + rr*8;
                *(float2*)(g_oh + ((size_t)(b*NS + q0 + m))*ND + h*HD + n) =
                    make_float2(c[mt][nt][rr*2], c[mt][nt][rr*2+1]);
            }
        }
}

// ---------------------------------------------------------------------------
extern "C" void kernel_launch(void* const* d_in, const int* in_sizes, int n_in,
                              void* d_out, int out_size) {
    const float* x     = (const float*)d_in[0];
    const float* qkv_w = (const float*)d_in[1];
    const float* qkv_b = (const float*)d_in[2];
    const float* out_w = (const float*)d_in[3];
    const float* out_b = (const float*)d_in[4];
    float* out  = (float*)d_out;
    float* attn = out + OUT_ELEMS;

    const int SM_MM = 4*2176*4 + 512;                    // 35328
    const int SM_KN = (4*8320 + 16896 + 256) * 4;        // 201728
    const int SM_SC = 4*4224*4 + 16896*4 + 128;          // 135296
    const int SM_AV = (2*8320 + 2*4160)*4 + 256*4;       // 100864
    cudaFuncSetAttribute(k_mm,     cudaFuncAttributeMaxDynamicSharedMemorySize, SM_MM);
    cudaFuncSetAttribute(k_knn,    cudaFuncAttributeMaxDynamicSharedMemorySize, SM_KN);
    cudaFuncSetAttribute(k_scores, cudaFuncAttributeMaxDynamicSharedMemorySize, SM_SC);
    cudaFuncSetAttribute(k_av,     cudaFuncAttributeMaxDynamicSharedMemorySize, SM_AV);

    k_mm    <<<dim3(24, 32), 256, SM_MM>>>(x, qkv_w, qkv_b, nullptr, 0);
    k_stats <<<32, 256>>>(x);
    k_knn   <<<dim3(16, 32), 256, SM_KN>>>(x);
    k_tls   <<<32, 256>>>();
    k_topk  <<<32, 1024>>>();
    k_scores<<<dim3(16, 32), 256, SM_SC>>>(attn);
    k_av    <<<dim3(16, 32), 256, SM_AV>>>(attn);
    k_mm    <<<dim3(8, 32), 256, SM_MM>>>(nullptr, out_w, out_b, out, 1);
}